// round 9
// baseline (speedup 1.0000x reference)
#include <cuda_runtime.h>
#include <cuda_fp16.h>
#include <math.h>
#include <stdint.h>

#define B    16
#define C    128
#define HH   128
#define WW   128
#define HW   (HH*WW)
#define KK   9
#define KCH  32
#define NCHUNK (C/KCH)

// Scratch. g_midh layout: [b][c][h][w] (same as R4 best)
__device__ __half g_midh[(size_t)B*C*HW];
__device__ __half g_wh[C*C];               // conv weights fp16 [o][k]
__device__ float  g_att[B*C];              // CA attention
__device__ float  g_t[B*C];                // hidden MLP activations
__device__ float  g_hid[B*16];             // CA hidden activations

__device__ __forceinline__ float lrelu(float v) { return v > 0.f ? v : 0.1f*v; }

__device__ __forceinline__ void cp16(void* dst, const void* src) {
    uint32_t d = (uint32_t)__cvta_generic_to_shared(dst);
    asm volatile("cp.async.cg.shared.global [%0], [%1], 16;" :: "r"(d), "l"(src));
}
__device__ __forceinline__ void cp_commit() {
    asm volatile("cp.async.commit_group;");
}

__device__ __forceinline__ void ldmatrix_x4(uint32_t* r, const void* p) {
    uint32_t a = (uint32_t)__cvta_generic_to_shared(p);
    asm volatile("ldmatrix.sync.aligned.m8n8.x4.shared.b16 {%0,%1,%2,%3}, [%4];"
                 : "=r"(r[0]), "=r"(r[1]), "=r"(r[2]), "=r"(r[3]) : "r"(a));
}
__device__ __forceinline__ void ldmatrix_x2_t(uint32_t* r, const void* p) {
    uint32_t a = (uint32_t)__cvta_generic_to_shared(p);
    asm volatile("ldmatrix.sync.aligned.m8n8.x2.trans.shared.b16 {%0,%1}, [%2];"
                 : "=r"(r[0]), "=r"(r[1]) : "r"(a));
}
__device__ __forceinline__ void mma_f16(float* d, const uint32_t* a, const uint32_t* b) {
    asm volatile(
        "mma.sync.aligned.m16n8k16.row.col.f32.f16.f16.f32 "
        "{%0,%1,%2,%3}, {%4,%5,%6,%7}, {%8,%9}, {%0,%1,%2,%3};"
        : "+f"(d[0]), "+f"(d[1]), "+f"(d[2]), "+f"(d[3])
        : "r"(a[0]), "r"(a[1]), "r"(a[2]), "r"(a[3]), "r"(b[0]), "r"(b[1]));
}

// ---------------------------------------------------------------------------
// P1: one block per MLP output j (144 = 128 t-outputs + 16 CA-hidden).
// Each warp handles 2 batches. grid = 144, block = 256.
// ---------------------------------------------------------------------------
__global__ void prep1_kernel(const float* __restrict__ deg,
                             const float* __restrict__ w1,
                             const float* __restrict__ caw1)
{
    const int j    = blockIdx.x;
    const int tid  = threadIdx.x;
    const int wid  = tid >> 5;
    const int lane = tid & 31;

    __shared__ float sdeg[B][C];

    #pragma unroll
    for (int i = tid; i < B*C; i += 256)
        ((float*)sdeg)[i] = deg[i];
    __syncthreads();

    const float* wrow = (j < 128) ? (w1 + j*C) : (caw1 + (j-128)*C);
    float w[4];
    #pragma unroll
    for (int u = 0; u < 4; ++u) w[u] = wrow[lane*4 + u];

    #pragma unroll
    for (int rep = 0; rep < 2; ++rep) {
        const int b = wid + rep*8;
        float acc = 0.f;
        #pragma unroll
        for (int u = 0; u < 4; ++u) acc += sdeg[b][lane*4 + u]*w[u];
        #pragma unroll
        for (int s = 16; s > 0; s >>= 1) acc += __shfl_xor_sync(0xffffffffu, acc, s);
        if (lane == 0) {
            if (j < 128) g_t[b*C + j]        = lrelu(acc);
            else         g_hid[b*16 + j-128] = lrelu(acc);
        }
    }
}

// ---------------------------------------------------------------------------
// P1b: CA attention sigmoid + fp16 weight conversion. grid = B, block = 256.
// ---------------------------------------------------------------------------
__global__ void prep1b_kernel(const float* __restrict__ caw2,
                              const float* __restrict__ convw)
{
    const int b   = blockIdx.x;
    const int tid = threadIdx.x;

    __shared__ float shid[16];
    if (tid < 16) shid[tid] = g_hid[b*16 + tid];
    __syncthreads();

    if (tid < C) {
        float acc = 0.f;
        const float* wrow = caw2 + tid*16;
        #pragma unroll
        for (int r = 0; r < 16; ++r) acc += shid[r]*wrow[r];
        g_att[b*C + tid] = 1.f/(1.f + expf(-acc));
    }

    {
        const int base = b*1024 + tid*4;
        float4 v = *(const float4*)(convw + base);
        g_wh[base+0] = __float2half(v.x);
        g_wh[base+1] = __float2half(v.y);
        g_wh[base+2] = __float2half(v.z);
        g_wh[base+3] = __float2half(v.w);
    }
}

// ---------------------------------------------------------------------------
// dwconv (+ fused kernel-coefficient dots): one block per (b,c) plane.
// grid = B*C, block = 256, 4 px/thread, fp16 output in [b][c][h][w].
// ---------------------------------------------------------------------------
__global__ void dwconv_kernel(const float* __restrict__ x0,
                              const float* __restrict__ w2)
{
    const int bc   = blockIdx.x;
    const int b    = bc >> 7;
    const int c    = bc & 127;
    const int tid  = threadIdx.x;
    const int wid  = tid >> 5;
    const int lane = tid & 31;

    __shared__ float sk[9];
    __shared__ float st[C];

    if (tid < C) st[tid] = g_t[b*C + tid];
    __syncthreads();

    for (int j = wid; j < KK; j += 8) {
        const float* wrow = w2 + (size_t)(c*KK + j)*C;
        float acc = 0.f;
        #pragma unroll
        for (int u = 0; u < 4; ++u) {
            const int idx = lane*4 + u;
            acc += st[idx]*wrow[idx];
        }
        #pragma unroll
        for (int s = 16; s > 0; s >>= 1) acc += __shfl_xor_sync(0xffffffffu, acc, s);
        if (lane == 0) sk[j] = acc;
    }
    __syncthreads();

    float k[9];
    #pragma unroll
    for (int i = 0; i < 9; ++i) k[i] = sk[i];

    const float* __restrict__ src = x0 + (size_t)bc*HW;
    __half* __restrict__ dst = g_midh + (size_t)bc*HW;

    for (int p4 = tid*4; p4 < HW; p4 += 256*4) {
        const int h  = p4 >> 7;
        const int w0 = p4 & (WW-1);
        float a0 = 0.f, a1 = 0.f, a2 = 0.f, a3 = 0.f;

        #pragma unroll
        for (int kh = 0; kh < 3; ++kh) {
            const int hh = h + kh - 1;
            if (hh < 0 || hh >= HH) continue;
            const float* row = src + hh*WW;
            float4 cv = *(const float4*)(row + w0);
            float vl = (w0 > 0)    ? row[w0-1] : 0.f;
            float vr = (w0 < WW-4) ? row[w0+4] : 0.f;
            const float k0 = k[kh*3+0], k1 = k[kh*3+1], k2 = k[kh*3+2];
            a0 += k0*vl   + k1*cv.x + k2*cv.y;
            a1 += k0*cv.x + k1*cv.y + k2*cv.z;
            a2 += k0*cv.y + k1*cv.z + k2*cv.w;
            a3 += k0*cv.z + k1*cv.w + k2*vr;
        }
        __half2 h01 = __floats2half2_rn(lrelu(a0), lrelu(a1));
        __half2 h23 = __floats2half2_rn(lrelu(a2), lrelu(a3));
        uint2 pk;
        pk.x = *(uint32_t*)&h01;
        pk.y = *(uint32_t*)&h23;
        *(uint2*)(dst + p4) = pk;
    }
}

// ---------------------------------------------------------------------------
// GEMM: fp16 mma m16n8k16, cp.async double-buffered (A+B per chunk) — R4 exact.
// Block tile M=128 x N=128, 8 warps of 64x32. grid = (HH, B), block = 256.
// ---------------------------------------------------------------------------
#define SA_STRIDE 40    // halves: 32 data + 8 pad
#define SB_STRIDE 136   // halves: 128 data + 8 pad

__global__ void __launch_bounds__(256, 2)
gemm_f16(const float* __restrict__ bias,
         const float* __restrict__ x0,
         float* __restrict__ out)
{
    __shared__ __align__(16) __half sA[2][C*SA_STRIDE];    // [o][k-chunk]
    __shared__ __align__(16) __half sB[2][KCH*SB_STRIDE];  // [k][p]

    const int b    = blockIdx.y;
    const int h    = blockIdx.x;
    const int tid  = threadIdx.x;
    const int wid  = tid >> 5;
    const int lane = tid & 31;
    const int g    = lane >> 2;
    const int tg   = lane & 3;
    const int wm0  = (wid >> 2) * 64;
    const int wn0  = (wid & 3) * 32;

    float d[4][4][4];
    #pragma unroll
    for (int mt = 0; mt < 4; ++mt)
        #pragma unroll
        for (int nt = 0; nt < 4; ++nt)
            #pragma unroll
            for (int r = 0; r < 4; ++r) d[mt][nt][r] = 0.f;

    const __half* __restrict__ midb = g_midh + ((size_t)b*C)*HW + h*WW;

    const int sbk = tid >> 3;            // 0..31 (k row)
    const int sbs = (tid & 7) * 2;       // seg pair within row
    const int sao = tid >> 1;            // 0..127 (o row)
    const int sas = (tid & 1) * 2;       // seg pair within row

#define LOAD_CHUNK(cc, buf) do {                                               \
        const __half* srcB = midb + (size_t)((cc)*KCH + sbk)*HW + sbs*8;       \
        __half* dstB = &sB[buf][sbk*SB_STRIDE + sbs*8];                        \
        cp16(dstB,     srcB);                                                  \
        cp16(dstB + 8, srcB + 8);                                              \
        const __half* srcA = g_wh + sao*C + (cc)*KCH + sas*8;                  \
        __half* dstA = &sA[buf][sao*SA_STRIDE + sas*8];                        \
        cp16(dstA,     srcA);                                                  \
        cp16(dstA + 8, srcA + 8);                                              \
        cp_commit();                                                           \
    } while (0)

    LOAD_CHUNK(0, 0);

    #pragma unroll
    for (int c = 0; c < NCHUNK; ++c) {
        const int buf = c & 1;
        if (c + 1 < NCHUNK) {
            LOAD_CHUNK(c + 1, (c + 1) & 1);
            asm volatile("cp.async.wait_group 1;");
        } else {
            asm volatile("cp.async.wait_group 0;");
        }
        __syncthreads();

        #pragma unroll
        for (int ks = 0; ks < KCH; ks += 16) {
            uint32_t af[4][4];
            const int arow = lane & 15;
            const int acol = ks + ((lane >> 4) << 3);
            #pragma unroll
            for (int mt = 0; mt < 4; ++mt)
                ldmatrix_x4(af[mt], &sA[buf][(wm0 + mt*16 + arow)*SA_STRIDE + acol]);

            uint32_t bf[4][2];
            const int brow = ks + (lane & 15);
            #pragma unroll
            for (int nt = 0; nt < 4; ++nt)
                ldmatrix_x2_t(bf[nt], &sB[buf][brow*SB_STRIDE + wn0 + nt*8]);

            #pragma unroll
            for (int mt = 0; mt < 4; ++mt)
                #pragma unroll
                for (int nt = 0; nt < 4; ++nt)
                    mma_f16(d[mt][nt], af[mt], bf[nt]);
        }
        __syncthreads();
    }

    // ---- fused epilogue: bias + x0*att residual (streaming) ----
    const int pix0 = h * WW;
    #pragma unroll
    for (int mt = 0; mt < 4; ++mt) {
        #pragma unroll
        for (int half = 0; half < 2; ++half) {
            const int o  = wm0 + mt*16 + g + half*8;
            const float bo = bias[o];
            const float at = g_att[b*C + o];
            const float* __restrict__ xrow = x0  + ((size_t)(b*C + o))*HW + pix0;
            float* __restrict__       orow = out + ((size_t)(b*C + o))*HW + pix0;
            #pragma unroll
            for (int nt = 0; nt < 4; ++nt) {
                const int cc2 = wn0 + nt*8 + 2*tg;
                float2 xv = __ldcs((const float2*)(xrow + cc2));
                float2 ov;
                ov.x = d[mt][nt][half*2 + 0] + bo + xv.x*at;
                ov.y = d[mt][nt][half*2 + 1] + bo + xv.y*at;
                __stcs((float2*)(orow + cc2), ov);
            }
        }
    }
}

// ---------------------------------------------------------------------------
extern "C" void kernel_launch(void* const* d_in, const int* in_sizes, int n_in,
                              void* d_out, int out_size)
{
    const float* x0    = (const float*)d_in[0];
    const float* deg   = (const float*)d_in[1];
    const float* w1    = (const float*)d_in[2];
    const float* w2    = (const float*)d_in[3];
    const float* convw = (const float*)d_in[4];
    const float* convb = (const float*)d_in[5];
    const float* caw1  = (const float*)d_in[6];
    const float* caw2  = (const float*)d_in[7];
    float* out = (float*)d_out;

    prep1_kernel<<<144, 256>>>(deg, w1, caw1);
    prep1b_kernel<<<B, 256>>>(caw2, convw);
    dwconv_kernel<<<B*C, 256>>>(x0, w2);
    gemm_f16<<<dim3(HH, B), 256>>>(convb, x0, out);
}

// round 10
// speedup vs baseline: 1.3604x; 1.3604x over previous
#include <cuda_runtime.h>
#include <cuda_fp16.h>
#include <math.h>
#include <stdint.h>

#define B    16
#define C    128
#define HH   128
#define WW   128
#define HW   (HH*WW)
#define KK   9
#define KCH  32
#define NCHUNK (C/KCH)

// Scratch. g_midh layout: [b][c][h][w]
__device__ __half g_midh[(size_t)B*C*HW];
__device__ __half g_wh[C*C];               // conv weights fp16 [o][k]
__device__ float  g_att[B*C];              // CA attention
__device__ float  g_t[B*C];                // hidden MLP activations
__device__ float  g_hid[B*16];             // CA hidden activations

__device__ __forceinline__ float lrelu(float v) { return v > 0.f ? v : 0.1f*v; }

__device__ __forceinline__ void cp16(void* dst, const void* src) {
    uint32_t d = (uint32_t)__cvta_generic_to_shared(dst);
    asm volatile("cp.async.cg.shared.global [%0], [%1], 16;" :: "r"(d), "l"(src));
}
__device__ __forceinline__ void cp_commit() {
    asm volatile("cp.async.commit_group;");
}

__device__ __forceinline__ void ldmatrix_x4(uint32_t* r, const void* p) {
    uint32_t a = (uint32_t)__cvta_generic_to_shared(p);
    asm volatile("ldmatrix.sync.aligned.m8n8.x4.shared.b16 {%0,%1,%2,%3}, [%4];"
                 : "=r"(r[0]), "=r"(r[1]), "=r"(r[2]), "=r"(r[3]) : "r"(a));
}
__device__ __forceinline__ void ldmatrix_x2_t(uint32_t* r, const void* p) {
    uint32_t a = (uint32_t)__cvta_generic_to_shared(p);
    asm volatile("ldmatrix.sync.aligned.m8n8.x2.trans.shared.b16 {%0,%1}, [%2];"
                 : "=r"(r[0]), "=r"(r[1]) : "r"(a));
}
__device__ __forceinline__ void mma_f16(float* d, const uint32_t* a, const uint32_t* b) {
    asm volatile(
        "mma.sync.aligned.m16n8k16.row.col.f32.f16.f16.f32 "
        "{%0,%1,%2,%3}, {%4,%5,%6,%7}, {%8,%9}, {%0,%1,%2,%3};"
        : "+f"(d[0]), "+f"(d[1]), "+f"(d[2]), "+f"(d[3])
        : "r"(a[0]), "r"(a[1]), "r"(a[2]), "r"(a[3]), "r"(b[0]), "r"(b[1]));
}

// ---------------------------------------------------------------------------
// P1: one block per MLP output j (144 = 128 t-outputs + 16 CA-hidden).
// Each warp handles 2 batches. grid = 144, block = 256.
// ---------------------------------------------------------------------------
__global__ void prep1_kernel(const float* __restrict__ deg,
                             const float* __restrict__ w1,
                             const float* __restrict__ caw1)
{
    const int j    = blockIdx.x;
    const int tid  = threadIdx.x;
    const int wid  = tid >> 5;
    const int lane = tid & 31;

    __shared__ float sdeg[B][C];

    #pragma unroll
    for (int i = tid; i < B*C; i += 256)
        ((float*)sdeg)[i] = deg[i];
    __syncthreads();

    const float* wrow = (j < 128) ? (w1 + j*C) : (caw1 + (j-128)*C);
    float w[4];
    #pragma unroll
    for (int u = 0; u < 4; ++u) w[u] = wrow[lane*4 + u];

    #pragma unroll
    for (int rep = 0; rep < 2; ++rep) {
        const int b = wid + rep*8;
        float acc = 0.f;
        #pragma unroll
        for (int u = 0; u < 4; ++u) acc += sdeg[b][lane*4 + u]*w[u];
        #pragma unroll
        for (int s = 16; s > 0; s >>= 1) acc += __shfl_xor_sync(0xffffffffu, acc, s);
        if (lane == 0) {
            if (j < 128) g_t[b*C + j]        = lrelu(acc);
            else         g_hid[b*16 + j-128] = lrelu(acc);
        }
    }
}

// ---------------------------------------------------------------------------
// P1b: CA attention sigmoid + fp16 weight conversion. grid = B, block = 256.
// ---------------------------------------------------------------------------
__global__ void prep1b_kernel(const float* __restrict__ caw2,
                              const float* __restrict__ convw)
{
    const int b   = blockIdx.x;
    const int tid = threadIdx.x;

    __shared__ float shid[16];
    if (tid < 16) shid[tid] = g_hid[b*16 + tid];
    __syncthreads();

    if (tid < C) {
        float acc = 0.f;
        const float* wrow = caw2 + tid*16;
        #pragma unroll
        for (int r = 0; r < 16; ++r) acc += shid[r]*wrow[r];
        g_att[b*C + tid] = 1.f/(1.f + expf(-acc));
    }

    {
        const int base = b*1024 + tid*4;
        float4 v = *(const float4*)(convw + base);
        g_wh[base+0] = __float2half(v.x);
        g_wh[base+1] = __float2half(v.y);
        g_wh[base+2] = __float2half(v.z);
        g_wh[base+3] = __float2half(v.w);
    }
}

// ---------------------------------------------------------------------------
// dwconv (+ fused kernel-coefficient dots): one block per (b,c) plane.
// grid = B*C, block = 256, 4 px/thread, fp16 output in [b][c][h][w].
// ---------------------------------------------------------------------------
__global__ void dwconv_kernel(const float* __restrict__ x0,
                              const float* __restrict__ w2)
{
    const int bc   = blockIdx.x;
    const int b    = bc >> 7;
    const int c    = bc & 127;
    const int tid  = threadIdx.x;
    const int wid  = tid >> 5;
    const int lane = tid & 31;

    __shared__ float sk[9];
    __shared__ float st[C];

    if (tid < C) st[tid] = g_t[b*C + tid];
    __syncthreads();

    for (int j = wid; j < KK; j += 8) {
        const float* wrow = w2 + (size_t)(c*KK + j)*C;
        float acc = 0.f;
        #pragma unroll
        for (int u = 0; u < 4; ++u) {
            const int idx = lane*4 + u;
            acc += st[idx]*wrow[idx];
        }
        #pragma unroll
        for (int s = 16; s > 0; s >>= 1) acc += __shfl_xor_sync(0xffffffffu, acc, s);
        if (lane == 0) sk[j] = acc;
    }
    __syncthreads();

    float k[9];
    #pragma unroll
    for (int i = 0; i < 9; ++i) k[i] = sk[i];

    const float* __restrict__ src = x0 + (size_t)bc*HW;
    __half* __restrict__ dst = g_midh + (size_t)bc*HW;

    for (int p4 = tid*4; p4 < HW; p4 += 256*4) {
        const int h  = p4 >> 7;
        const int w0 = p4 & (WW-1);
        float a0 = 0.f, a1 = 0.f, a2 = 0.f, a3 = 0.f;

        #pragma unroll
        for (int kh = 0; kh < 3; ++kh) {
            const int hh = h + kh - 1;
            if (hh < 0 || hh >= HH) continue;
            const float* row = src + hh*WW;
            float4 cv = *(const float4*)(row + w0);
            float vl = (w0 > 0)    ? row[w0-1] : 0.f;
            float vr = (w0 < WW-4) ? row[w0+4] : 0.f;
            const float k0 = k[kh*3+0], k1 = k[kh*3+1], k2 = k[kh*3+2];
            a0 += k0*vl   + k1*cv.x + k2*cv.y;
            a1 += k0*cv.x + k1*cv.y + k2*cv.z;
            a2 += k0*cv.y + k1*cv.z + k2*cv.w;
            a3 += k0*cv.z + k1*cv.w + k2*vr;
        }
        __half2 h01 = __floats2half2_rn(lrelu(a0), lrelu(a1));
        __half2 h23 = __floats2half2_rn(lrelu(a2), lrelu(a3));
        uint2 pk;
        pk.x = *(uint32_t*)&h01;
        pk.y = *(uint32_t*)&h23;
        *(uint2*)(dst + p4) = pk;
    }
}

// ---------------------------------------------------------------------------
// GEMM: fp16 mma m16n8k16, cp.async double-buffered (A+B per chunk).
// EXACT R4 kernel (plain epilogue loads/stores — no cache hints).
// Block tile M=128 x N=128, 8 warps of 64x32. grid = (HH, B), block = 256.
// ---------------------------------------------------------------------------
#define SA_STRIDE 40    // halves: 32 data + 8 pad
#define SB_STRIDE 136   // halves: 128 data + 8 pad

__global__ void __launch_bounds__(256, 2)
gemm_f16(const float* __restrict__ bias,
         const float* __restrict__ x0,
         float* __restrict__ out)
{
    __shared__ __align__(16) __half sA[2][C*SA_STRIDE];    // [o][k-chunk]
    __shared__ __align__(16) __half sB[2][KCH*SB_STRIDE];  // [k][p]

    const int b    = blockIdx.y;
    const int h    = blockIdx.x;
    const int tid  = threadIdx.x;
    const int wid  = tid >> 5;
    const int lane = tid & 31;
    const int g    = lane >> 2;
    const int tg   = lane & 3;
    const int wm0  = (wid >> 2) * 64;
    const int wn0  = (wid & 3) * 32;

    float d[4][4][4];
    #pragma unroll
    for (int mt = 0; mt < 4; ++mt)
        #pragma unroll
        for (int nt = 0; nt < 4; ++nt)
            #pragma unroll
            for (int r = 0; r < 4; ++r) d[mt][nt][r] = 0.f;

    const __half* __restrict__ midb = g_midh + ((size_t)b*C)*HW + h*WW;

    const int sbk = tid >> 3;            // 0..31 (k row)
    const int sbs = (tid & 7) * 2;       // seg pair within row
    const int sao = tid >> 1;            // 0..127 (o row)
    const int sas = (tid & 1) * 2;       // seg pair within row

#define LOAD_CHUNK(cc, buf) do {                                               \
        const __half* srcB = midb + (size_t)((cc)*KCH + sbk)*HW + sbs*8;       \
        __half* dstB = &sB[buf][sbk*SB_STRIDE + sbs*8];                        \
        cp16(dstB,     srcB);                                                  \
        cp16(dstB + 8, srcB + 8);                                              \
        const __half* srcA = g_wh + sao*C + (cc)*KCH + sas*8;                  \
        __half* dstA = &sA[buf][sao*SA_STRIDE + sas*8];                        \
        cp16(dstA,     srcA);                                                  \
        cp16(dstA + 8, srcA + 8);                                              \
        cp_commit();                                                           \
    } while (0)

    LOAD_CHUNK(0, 0);

    #pragma unroll
    for (int c = 0; c < NCHUNK; ++c) {
        const int buf = c & 1;
        if (c + 1 < NCHUNK) {
            LOAD_CHUNK(c + 1, (c + 1) & 1);
            asm volatile("cp.async.wait_group 1;");
        } else {
            asm volatile("cp.async.wait_group 0;");
        }
        __syncthreads();

        #pragma unroll
        for (int ks = 0; ks < KCH; ks += 16) {
            uint32_t af[4][4];
            const int arow = lane & 15;
            const int acol = ks + ((lane >> 4) << 3);
            #pragma unroll
            for (int mt = 0; mt < 4; ++mt)
                ldmatrix_x4(af[mt], &sA[buf][(wm0 + mt*16 + arow)*SA_STRIDE + acol]);

            uint32_t bf[4][2];
            const int brow = ks + (lane & 15);
            #pragma unroll
            for (int nt = 0; nt < 4; ++nt)
                ldmatrix_x2_t(bf[nt], &sB[buf][brow*SB_STRIDE + wn0 + nt*8]);

            #pragma unroll
            for (int mt = 0; mt < 4; ++mt)
                #pragma unroll
                for (int nt = 0; nt < 4; ++nt)
                    mma_f16(d[mt][nt], af[mt], bf[nt]);
        }
        __syncthreads();
    }

    // ---- fused epilogue: bias + x0*att residual (plain loads/stores) ----
    const int pix0 = h * WW;
    #pragma unroll
    for (int mt = 0; mt < 4; ++mt) {
        #pragma unroll
        for (int half = 0; half < 2; ++half) {
            const int o  = wm0 + mt*16 + g + half*8;
            const float bo = bias[o];
            const float at = g_att[b*C + o];
            const float* __restrict__ xrow = x0  + ((size_t)(b*C + o))*HW + pix0;
            float* __restrict__       orow = out + ((size_t)(b*C + o))*HW + pix0;
            #pragma unroll
            for (int nt = 0; nt < 4; ++nt) {
                const int cc2 = wn0 + nt*8 + 2*tg;
                float2 xv = *(const float2*)(xrow + cc2);
                float2 ov;
                ov.x = d[mt][nt][half*2 + 0] + bo + xv.x*at;
                ov.y = d[mt][nt][half*2 + 1] + bo + xv.y*at;
                *(float2*)(orow + cc2) = ov;
            }
        }
    }
}

// ---------------------------------------------------------------------------
extern "C" void kernel_launch(void* const* d_in, const int* in_sizes, int n_in,
                              void* d_out, int out_size)
{
    const float* x0    = (const float*)d_in[0];
    const float* deg   = (const float*)d_in[1];
    const float* w1    = (const float*)d_in[2];
    const float* w2    = (const float*)d_in[3];
    const float* convw = (const float*)d_in[4];
    const float* convb = (const float*)d_in[5];
    const float* caw1  = (const float*)d_in[6];
    const float* caw2  = (const float*)d_in[7];
    float* out = (float*)d_out;

    prep1_kernel<<<144, 256>>>(deg, w1, caw1);
    prep1b_kernel<<<B, 256>>>(caw2, convw);
    dwconv_kernel<<<B*C, 256>>>(x0, w2);
    gemm_f16<<<dim3(HH, B), 256>>>(convb, x0, out);
}

// round 12
// speedup vs baseline: 1.4045x; 1.0324x over previous
#include <cuda_runtime.h>
#include <cuda_fp16.h>
#include <math.h>
#include <stdint.h>

#define B    16
#define C    128
#define HH   128
#define WW   128
#define HW   (HH*WW)
#define KK   9
#define KCH  32
#define NCHUNK (C/KCH)

// Scratch. g_midh layout: [b][c][h][w]
__device__ __half g_midh[(size_t)B*C*HW];
__device__ __half g_wh[C*C];               // conv weights fp16 [o][k]
__device__ float  g_att[B*C];              // CA attention
__device__ float  g_t[B*C];                // hidden MLP activations
__device__ float  g_hid[B*16];             // CA hidden activations

__device__ __forceinline__ float lrelu(float v) { return v > 0.f ? v : 0.1f*v; }

__device__ __forceinline__ void cp16(void* dst, const void* src) {
    uint32_t d = (uint32_t)__cvta_generic_to_shared(dst);
    asm volatile("cp.async.cg.shared.global [%0], [%1], 16;" :: "r"(d), "l"(src));
}
__device__ __forceinline__ void cp_commit() {
    asm volatile("cp.async.commit_group;");
}

__device__ __forceinline__ void ldmatrix_x4(uint32_t* r, const void* p) {
    uint32_t a = (uint32_t)__cvta_generic_to_shared(p);
    asm volatile("ldmatrix.sync.aligned.m8n8.x4.shared.b16 {%0,%1,%2,%3}, [%4];"
                 : "=r"(r[0]), "=r"(r[1]), "=r"(r[2]), "=r"(r[3]) : "r"(a));
}
__device__ __forceinline__ void ldmatrix_x2_t(uint32_t* r, const void* p) {
    uint32_t a = (uint32_t)__cvta_generic_to_shared(p);
    asm volatile("ldmatrix.sync.aligned.m8n8.x2.trans.shared.b16 {%0,%1}, [%2];"
                 : "=r"(r[0]), "=r"(r[1]) : "r"(a));
}
__device__ __forceinline__ void mma_f16(float* d, const uint32_t* a, const uint32_t* b) {
    asm volatile(
        "mma.sync.aligned.m16n8k16.row.col.f32.f16.f16.f32 "
        "{%0,%1,%2,%3}, {%4,%5,%6,%7}, {%8,%9}, {%0,%1,%2,%3};"
        : "+f"(d[0]), "+f"(d[1]), "+f"(d[2]), "+f"(d[3])
        : "r"(a[0]), "r"(a[1]), "r"(a[2]), "r"(a[3]), "r"(b[0]), "r"(b[1]));
}

// ---------------------------------------------------------------------------
// P1: one block per MLP output j (144 = 128 t-outputs + 16 CA-hidden).
// ---------------------------------------------------------------------------
__global__ void prep1_kernel(const float* __restrict__ deg,
                             const float* __restrict__ w1,
                             const float* __restrict__ caw1)
{
    const int j    = blockIdx.x;
    const int tid  = threadIdx.x;
    const int wid  = tid >> 5;
    const int lane = tid & 31;

    __shared__ float sdeg[B][C];

    #pragma unroll
    for (int i = tid; i < B*C; i += 256)
        ((float*)sdeg)[i] = deg[i];
    __syncthreads();

    const float* wrow = (j < 128) ? (w1 + j*C) : (caw1 + (j-128)*C);
    float w[4];
    #pragma unroll
    for (int u = 0; u < 4; ++u) w[u] = wrow[lane*4 + u];

    #pragma unroll
    for (int rep = 0; rep < 2; ++rep) {
        const int b = wid + rep*8;
        float acc = 0.f;
        #pragma unroll
        for (int u = 0; u < 4; ++u) acc += sdeg[b][lane*4 + u]*w[u];
        #pragma unroll
        for (int s = 16; s > 0; s >>= 1) acc += __shfl_xor_sync(0xffffffffu, acc, s);
        if (lane == 0) {
            if (j < 128) g_t[b*C + j]        = lrelu(acc);
            else         g_hid[b*16 + j-128] = lrelu(acc);
        }
    }
}

// ---------------------------------------------------------------------------
// P1b: CA attention sigmoid + fp16 weight conversion. grid = B, block = 256.
// ---------------------------------------------------------------------------
__global__ void prep1b_kernel(const float* __restrict__ caw2,
                              const float* __restrict__ convw)
{
    const int b   = blockIdx.x;
    const int tid = threadIdx.x;

    __shared__ float shid[16];
    if (tid < 16) shid[tid] = g_hid[b*16 + tid];
    __syncthreads();

    if (tid < C) {
        float acc = 0.f;
        const float* wrow = caw2 + tid*16;
        #pragma unroll
        for (int r = 0; r < 16; ++r) acc += shid[r]*wrow[r];
        g_att[b*C + tid] = 1.f/(1.f + expf(-acc));
    }

    {
        const int base = b*1024 + tid*4;
        float4 v = *(const float4*)(convw + base);
        g_wh[base+0] = __float2half(v.x);
        g_wh[base+1] = __float2half(v.y);
        g_wh[base+2] = __float2half(v.z);
        g_wh[base+3] = __float2half(v.w);
    }
}

// ---------------------------------------------------------------------------
// dwconv (+ fused kernel-coefficient dots): one block per (b,c) plane.
// ---------------------------------------------------------------------------
__global__ void dwconv_kernel(const float* __restrict__ x0,
                              const float* __restrict__ w2)
{
    const int bc   = blockIdx.x;
    const int b    = bc >> 7;
    const int c    = bc & 127;
    const int tid  = threadIdx.x;
    const int wid  = tid >> 5;
    const int lane = tid & 31;

    __shared__ float sk[9];
    __shared__ float st[C];

    if (tid < C) st[tid] = g_t[b*C + tid];
    __syncthreads();

    for (int j = wid; j < KK; j += 8) {
        const float* wrow = w2 + (size_t)(c*KK + j)*C;
        float acc = 0.f;
        #pragma unroll
        for (int u = 0; u < 4; ++u) {
            const int idx = lane*4 + u;
            acc += st[idx]*wrow[idx];
        }
        #pragma unroll
        for (int s = 16; s > 0; s >>= 1) acc += __shfl_xor_sync(0xffffffffu, acc, s);
        if (lane == 0) sk[j] = acc;
    }
    __syncthreads();

    float k[9];
    #pragma unroll
    for (int i = 0; i < 9; ++i) k[i] = sk[i];

    const float* __restrict__ src = x0 + (size_t)bc*HW;
    __half* __restrict__ dst = g_midh + (size_t)bc*HW;

    for (int p4 = tid*4; p4 < HW; p4 += 256*4) {
        const int h  = p4 >> 7;
        const int w0 = p4 & (WW-1);
        float a0 = 0.f, a1 = 0.f, a2 = 0.f, a3 = 0.f;

        #pragma unroll
        for (int kh = 0; kh < 3; ++kh) {
            const int hh = h + kh - 1;
            if (hh < 0 || hh >= HH) continue;
            const float* row = src + hh*WW;
            float4 cv = *(const float4*)(row + w0);
            float vl = (w0 > 0)    ? row[w0-1] : 0.f;
            float vr = (w0 < WW-4) ? row[w0+4] : 0.f;
            const float k0 = k[kh*3+0], k1 = k[kh*3+1], k2 = k[kh*3+2];
            a0 += k0*vl   + k1*cv.x + k2*cv.y;
            a1 += k0*cv.x + k1*cv.y + k2*cv.z;
            a2 += k0*cv.y + k1*cv.z + k2*cv.w;
            a3 += k0*cv.z + k1*cv.w + k2*vr;
        }
        __half2 h01 = __floats2half2_rn(lrelu(a0), lrelu(a1));
        __half2 h23 = __floats2half2_rn(lrelu(a2), lrelu(a3));
        uint2 pk;
        pk.x = *(uint32_t*)&h01;
        pk.y = *(uint32_t*)&h23;
        *(uint2*)(dst + p4) = pk;
    }
}

// ---------------------------------------------------------------------------
// GEMM: fp16 mma m16n8k16, 3-stage cp.async pipeline, XOR-swizzled smem.
// Correct drain: at iter c, issued groups = chunks 0..min(c+1,3); chunk c
// must be resident -> allowed pending = 1,1,1,0.
// Block tile M=128 x N=128, 8 warps of 64x32. grid = (HH, B), block = 256.
// Static smem = 3*(8192+8192) = 49152 B.
// ---------------------------------------------------------------------------
__global__ void __launch_bounds__(256, 2)
gemm_f16(const float* __restrict__ bias,
         const float* __restrict__ x0,
         float* __restrict__ out)
{
    __shared__ __align__(16) __half sA[3][C*KCH];     // 3 x 8192 B
    __shared__ __align__(16) __half sB[3][KCH*128];   // 3 x 8192 B

    const int b    = blockIdx.y;
    const int h    = blockIdx.x;
    const int tid  = threadIdx.x;
    const int wid  = tid >> 5;
    const int lane = tid & 31;
    const int g    = lane >> 2;
    const int tg   = lane & 3;
    const int wm0  = (wid >> 2) * 64;
    const int wn0  = (wid & 3) * 32;

    float d[4][4][4];
    #pragma unroll
    for (int mt = 0; mt < 4; ++mt)
        #pragma unroll
        for (int nt = 0; nt < 4; ++nt)
            #pragma unroll
            for (int r = 0; r < 4; ++r) d[mt][nt][r] = 0.f;

    const __half* __restrict__ midb = g_midh + ((size_t)b*C)*HW + h*WW;

    const int sbk = tid >> 3;            // 0..31 (k row)
    const int sbs = (tid & 7) * 2;       // 2 units of 16B per thread
    const int sao = tid >> 1;            // 0..127 (o row)
    const int sas = (tid & 1) * 2;       // 2 units of 16B per thread
    const int aswz = (sao >> 1) & 3;     // A swizzle key for this row
    const int bswz = sbk & 7;            // B swizzle key for this row

#define LOAD_CHUNK(cc, st) do {                                                \
        const __half* srcB = midb + (size_t)((cc)*KCH + sbk)*HW;               \
        __half* dstB = &sB[st][sbk*128];                                       \
        cp16(dstB + ((sbs    ) ^ bswz)*8, srcB + (sbs    )*8);                 \
        cp16(dstB + ((sbs + 1) ^ bswz)*8, srcB + (sbs + 1)*8);                 \
        const __half* srcA = g_wh + sao*C + (cc)*KCH;                          \
        __half* dstA = &sA[st][sao*KCH];                                       \
        cp16(dstA + ((sas    ) ^ aswz)*8, srcA + (sas    )*8);                 \
        cp16(dstA + ((sas + 1) ^ aswz)*8, srcA + (sas + 1)*8);                 \
        cp_commit();                                                           \
    } while (0)

    // prologue: 2 stages ahead
    LOAD_CHUNK(0, 0);
    LOAD_CHUNK(1, 1);

    #pragma unroll
    for (int c = 0; c < NCHUNK; ++c) {
        const int st = c % 3;
        if (c < NCHUNK - 1)
            asm volatile("cp.async.wait_group 1;");   // chunk c resident, c+1 may fly
        else
            asm volatile("cp.async.wait_group 0;");
        __syncthreads();

        #pragma unroll
        for (int ks = 0; ks < KCH; ks += 16) {
            uint32_t af[4][4];
            const int arow = lane & 15;
            const int au   = (ks >> 3) + (lane >> 4);     // logical A unit 0..3
            #pragma unroll
            for (int mt = 0; mt < 4; ++mt) {
                const int r = wm0 + mt*16 + arow;
                ldmatrix_x4(af[mt], &sA[st][r*KCH + ((au ^ ((r >> 1) & 3)) << 3)]);
            }

            uint32_t bf[4][2];
            const int brow = ks + (lane & 15);
            #pragma unroll
            for (int nt = 0; nt < 4; ++nt) {
                const int un = (wn0 + nt*8) >> 3;          // logical B unit 0..15
                ldmatrix_x2_t(bf[nt], &sB[st][brow*128 + ((un ^ (brow & 7)) << 3)]);
            }

            #pragma unroll
            for (int mt = 0; mt < 4; ++mt)
                #pragma unroll
                for (int nt = 0; nt < 4; ++nt)
                    mma_f16(d[mt][nt], af[mt], bf[nt]);
        }
        __syncthreads();   // all warps done with stage st before it is reused

        if (c + 2 < NCHUNK)
            LOAD_CHUNK(c + 2, (c + 2) % 3);
    }

    // ---- fused epilogue: bias + x0*att residual (plain loads/stores) ----
    const int pix0 = h * WW;
    #pragma unroll
    for (int mt = 0; mt < 4; ++mt) {
        #pragma unroll
        for (int half = 0; half < 2; ++half) {
            const int o  = wm0 + mt*16 + g + half*8;
            const float bo = bias[o];
            const float at = g_att[b*C + o];
            const float* __restrict__ xrow = x0  + ((size_t)(b*C + o))*HW + pix0;
            float* __restrict__       orow = out + ((size_t)(b*C + o))*HW + pix0;
            #pragma unroll
            for (int nt = 0; nt < 4; ++nt) {
                const int cc2 = wn0 + nt*8 + 2*tg;
                float2 xv = *(const float2*)(xrow + cc2);
                float2 ov;
                ov.x = d[mt][nt][half*2 + 0] + bo + xv.x*at;
                ov.y = d[mt][nt][half*2 + 1] + bo + xv.y*at;
                *(float2*)(orow + cc2) = ov;
            }
        }
    }
}

// ---------------------------------------------------------------------------
extern "C" void kernel_launch(void* const* d_in, const int* in_sizes, int n_in,
                              void* d_out, int out_size)
{
    const float* x0    = (const float*)d_in[0];
    const float* deg   = (const float*)d_in[1];
    const float* w1    = (const float*)d_in[2];
    const float* w2    = (const float*)d_in[3];
    const float* convw = (const float*)d_in[4];
    const float* convb = (const float*)d_in[5];
    const float* caw1  = (const float*)d_in[6];
    const float* caw2  = (const float*)d_in[7];
    float* out = (float*)d_out;

    prep1_kernel<<<144, 256>>>(deg, w1, caw1);
    prep1b_kernel<<<B, 256>>>(caw2, convw);
    dwconv_kernel<<<B*C, 256>>>(x0, w2);
    gemm_f16<<<dim3(HH, B), 256>>>(convb, x0, out);
}